// round 10
// baseline (speedup 1.0000x reference)
#include <cuda_runtime.h>
#include <cuda_fp16.h>
#include <cstdint>

#define TPB 512

// smem layout
#define OF_WC 0u             // 32KB fp16 Wcf (128 rows x 256B, swizzled)
#define OF_WF 32768u         // 32KB fp16 Wfc
#define OF_WD 65536u         // 8KB  fp16 Wdf (128 rows x 64B, swizzled), persistent
#define SLICE(p) (73728u + (uint32_t)(p) * 18432u)   // per-node slice, 8 slices
//   slice+0     : fp16 src 32x128 (8KB)
//   slice+8192  : fp16 he  32x32  (2KB)
//   slice+10240 : fp16 h   32x128 (8KB)
#define OF_BC 221184u
#define OF_BD 221696u
#define OF_BF 222208u
#define SMEM_BYTES 222720u

__device__ __forceinline__ void ldsm4(uint32_t r[4], uint32_t a) {
    asm volatile("ldmatrix.sync.aligned.m8n8.x4.shared.b16 {%0,%1,%2,%3}, [%4];"
                 : "=r"(r[0]), "=r"(r[1]), "=r"(r[2]), "=r"(r[3]) : "r"(a));
}

__device__ __forceinline__ void stsm4(uint32_t a, uint32_t r0, uint32_t r1,
                                      uint32_t r2, uint32_t r3) {
    asm volatile("stmatrix.sync.aligned.m8n8.x4.shared.b16 [%0], {%1,%2,%3,%4};"
                 :: "r"(a), "r"(r0), "r"(r1), "r"(r2), "r"(r3) : "memory");
}

__device__ __forceinline__ void mma16(float* c, const uint32_t* a, uint32_t b0, uint32_t b1) {
    asm volatile(
        "mma.sync.aligned.m16n8k16.row.col.f32.f16.f16.f32 "
        "{%0,%1,%2,%3}, {%4,%5,%6,%7}, {%8,%9}, {%0,%1,%2,%3};\n"
        : "+f"(c[0]), "+f"(c[1]), "+f"(c[2]), "+f"(c[3])
        : "r"(a[0]), "r"(a[1]), "r"(a[2]), "r"(a[3]), "r"(b0), "r"(b1));
}

__device__ __forceinline__ float ftanh(float x) {
    float r;
    asm("tanh.approx.f32 %0, %1;" : "=f"(r) : "f"(x));
    return r;
}

__device__ __forceinline__ uint32_t pack2(float a, float b) {
    __half2 h = __floats2half2_rn(a, b);
    return *(uint32_t*)&h;
}
__device__ __forceinline__ float2 unp2(uint32_t u) {
    __half2 h = *(__half2*)&u;
    return __half22float2(h);
}

// pair-scoped named barrier (2 warps = 64 threads per node)
__device__ __forceinline__ void pbar(int pair) {
    asm volatile("bar.sync %0, 64;" :: "r"(pair + 1) : "memory");
}

// 256B-row swizzled addr (128 fp16 cols): ch 0..15
__device__ __forceinline__ uint32_t a16(uint32_t row, uint32_t ch) {
    return row * 256u + ((ch ^ (row & 7u)) << 4);
}
// 64B-row swizzled addr (32 fp16 cols): ch 0..3
__device__ __forceinline__ uint32_t h16(uint32_t row, uint32_t ch) {
    return row * 64u + ((ch ^ ((row >> 1) & 3u)) << 4);
}

__global__ void __launch_bounds__(TPB, 1)
dtnn_kernel(const float* __restrict__ gsrc, const float* __restrict__ ghe,
            const float* __restrict__ Wcf,  const float* __restrict__ bcf,
            const float* __restrict__ Wdf,  const float* __restrict__ bdf,
            const float* __restrict__ Wfc,  const float* __restrict__ bfc,
            float* __restrict__ out, int ntiles)
{
    extern __shared__ __align__(1024) unsigned char sm[];
    uint32_t smb;
    asm("{.reg .u64 t; cvta.to.shared.u64 t, %1; cvt.u32.u64 %0, t;}"
        : "=r"(smb) : "l"(sm));

    float* bC = (float*)(sm + OF_BC);
    float* bD = (float*)(sm + OF_BD);
    float* bF = (float*)(sm + OF_BF);

    const int tid  = threadIdx.x;
    const int lane = tid & 31;
    const int wid  = tid >> 5;
    const int tg   = lane & 3;
    const int pair = wid >> 1;            // node within tile; owns rows [32p, 32p+32)
    const int ptid = tid & 63;
    const int n0   = (wid & 1) * 64;      // column half
    const int grid = gridDim.x;

    // ---- one-time weight + bias staging (CTA-wide) ----
    for (int i = tid; i < 2048; i += TPB) {
        int row = i >> 4, ch = i & 15;
        float4 u = ((const float4*)Wcf)[row * 32 + ch * 2];
        float4 v = ((const float4*)Wcf)[row * 32 + ch * 2 + 1];
        uint4 w = {pack2(u.x, u.y), pack2(u.z, u.w), pack2(v.x, v.y), pack2(v.z, v.w)};
        *(uint4*)(sm + OF_WC + a16(row, ch)) = w;
        u = ((const float4*)Wfc)[row * 32 + ch * 2];
        v = ((const float4*)Wfc)[row * 32 + ch * 2 + 1];
        uint4 w2 = {pack2(u.x, u.y), pack2(u.z, u.w), pack2(v.x, v.y), pack2(v.z, v.w)};
        *(uint4*)(sm + OF_WF + a16(row, ch)) = w2;
    }
    for (int i = tid; i < 512; i += TPB) {
        int row = i >> 2, ch = i & 3;
        float4 u = ((const float4*)Wdf)[row * 8 + ch * 2];
        float4 v = ((const float4*)Wdf)[row * 8 + ch * 2 + 1];
        uint4 w = {pack2(u.x, u.y), pack2(u.z, u.w), pack2(v.x, v.y), pack2(v.z, v.w)};
        *(uint4*)(sm + OF_WD + h16(row, ch)) = w;
    }
    if (tid < 128) { bC[tid] = bcf[tid]; bD[tid] = bdf[tid]; bF[tid] = bfc[tid]; }
    __syncthreads();

    // ---- per-lane ldmatrix constants ----
    const uint32_t mrow = (uint32_t)((lane & 7) | (((lane >> 3) & 1) << 3));
    const uint32_t ksel = (uint32_t)((lane >> 4) & 1);
    const uint32_t key8 = mrow & 7u;
    const uint32_t keyh = (mrow >> 1) & 3u;

    const uint32_t slice = smb + SLICE(pair);
    const uint32_t srcB = slice + mrow * 256u;            // src A rows 0-15 (rows 16-31: +4096)
    const uint32_t heB  = slice + 8192u + mrow * 64u;     // he A rows 0-15 (+1024 for 16-31)
    const uint32_t hBa  = slice + 10240u + mrow * 256u;   // h A
    const uint32_t wc0  = smb + OF_WC + ((uint32_t)n0 + mrow) * 256u;  // +p*4096
    const uint32_t wf0  = smb + OF_WF + ((uint32_t)n0 + mrow) * 256u;
    const uint32_t wd0  = smb + OF_WD + ((uint32_t)n0 + mrow) * 64u;   // +p*1024
    const uint32_t srow = (uint32_t)(((lane >> 4) & 1) * 16 + ((lane >> 3) & 1) * 8
                                     + (lane & 7));

    for (int tile = blockIdx.x; tile < ntiles; tile += grid) {
        // 0. both warps of the pair done with previous tile's smem before overwrite
        pbar(pair);

        // 1. convert: global fp32 -> fp16 swizzled smem (own 32-row slice only)
        {
            const float4* sp = (const float4*)(gsrc + (size_t)tile * 32768 + pair * 4096);
            #pragma unroll
            for (int it = 0; it < 8; it++) {
                int i = ptid + it * 64;            // 512 output 16B chunks
                int row = i >> 4, ch = i & 15;
                float4 u = sp[row * 32 + ch * 2];
                float4 v = sp[row * 32 + ch * 2 + 1];
                uint4 w = {pack2(u.x, u.y), pack2(u.z, u.w),
                           pack2(v.x, v.y), pack2(v.z, v.w)};
                *(uint4*)(sm + (slice - smb) + a16((uint32_t)row, (uint32_t)ch)) = w;
            }
            const float4* hp = (const float4*)(ghe + (size_t)tile * 8192 + pair * 1024);
            #pragma unroll
            for (int it = 0; it < 2; it++) {
                int i = ptid + it * 64;            // 128 chunks
                int row = i >> 2, ch = i & 3;
                float4 u = hp[row * 8 + ch * 2];
                float4 v = hp[row * 8 + ch * 2 + 1];
                uint4 w = {pack2(u.x, u.y), pack2(u.z, u.w),
                           pack2(v.x, v.y), pack2(v.z, v.w)};
                *(uint4*)(sm + (slice - smb) + 8192u + h16((uint32_t)row, (uint32_t)ch)) = w;
            }
        }
        pbar(pair);    // fp16 tiles visible to both warps

        // 2. GEMM2: e = he @ Wdf^T, then pack (e + bdf) to half2 (32 regs)
        uint32_t accEp[2][8][2];
        {
            float accE[2][8][4];
            #pragma unroll
            for (int mt = 0; mt < 2; mt++)
                #pragma unroll
                for (int nt = 0; nt < 8; nt++)
                    accE[mt][nt][0] = accE[mt][nt][1] = accE[mt][nt][2] = accE[mt][nt][3] = 0.f;
            #pragma unroll
            for (int kt = 0; kt < 2; kt++) {
                uint32_t A0[4], A1[4];
                uint32_t ua = ((2u * kt + ksel) ^ keyh) << 4;
                ldsm4(A0, heB + ua);
                ldsm4(A1, heB + 1024u + ua);
                #pragma unroll
                for (int p = 0; p < 4; p++) {
                    uint32_t B[4];
                    ldsm4(B, wd0 + (uint32_t)p * 1024u + ua);
                    mma16(accE[0][2 * p],     A0, B[0], B[2]);
                    mma16(accE[0][2 * p + 1], A0, B[1], B[3]);
                    mma16(accE[1][2 * p],     A1, B[0], B[2]);
                    mma16(accE[1][2 * p + 1], A1, B[1], B[3]);
                }
            }
            #pragma unroll
            for (int nt = 0; nt < 8; nt++) {
                int c = n0 + nt * 8 + 2 * tg;
                float2 bd2 = *(float2*)(bD + c);
                #pragma unroll
                for (int mt = 0; mt < 2; mt++) {
                    accEp[mt][nt][0] = pack2(accE[mt][nt][0] + bd2.x, accE[mt][nt][1] + bd2.y);
                    accEp[mt][nt][1] = pack2(accE[mt][nt][2] + bd2.x, accE[mt][nt][3] + bd2.y);
                }
            }
        }

        // 3. GEMM1: c = src @ Wcf^T  (B loaded per-p to cap transients)
        float accC[2][8][4];
        #pragma unroll
        for (int mt = 0; mt < 2; mt++)
            #pragma unroll
            for (int nt = 0; nt < 8; nt++)
                accC[mt][nt][0] = accC[mt][nt][1] = accC[mt][nt][2] = accC[mt][nt][3] = 0.f;
        #pragma unroll
        for (int kt = 0; kt < 8; kt++) {
            uint32_t A0[4], A1[4];
            uint32_t ua = ((2u * kt + ksel) ^ key8) << 4;
            ldsm4(A0, srcB + ua);
            ldsm4(A1, srcB + 4096u + ua);
            #pragma unroll
            for (int p = 0; p < 4; p++) {
                uint32_t B[4];
                ldsm4(B, wc0 + (uint32_t)p * 4096u + ua);
                mma16(accC[0][2 * p],     A0, B[0], B[2]);
                mma16(accC[0][2 * p + 1], A0, B[1], B[3]);
                mma16(accC[1][2 * p],     A1, B[0], B[2]);
                mma16(accC[1][2 * p + 1], A1, B[1], B[3]);
            }
        }

        // 4. gate: h = (c + bcf) * e  -> h buffer via stmatrix
        #pragma unroll
        for (int nt = 0; nt < 8; nt++) {
            int c = n0 + nt * 8 + 2 * tg;
            float2 bc2 = *(float2*)(bC + c);
            float2 e00 = unp2(accEp[0][nt][0]);
            float2 e01 = unp2(accEp[0][nt][1]);
            float2 e10 = unp2(accEp[1][nt][0]);
            float2 e11 = unp2(accEp[1][nt][1]);
            uint32_t p0 = pack2((accC[0][nt][0] + bc2.x) * e00.x,
                                (accC[0][nt][1] + bc2.y) * e00.y);
            uint32_t p1 = pack2((accC[0][nt][2] + bc2.x) * e01.x,
                                (accC[0][nt][3] + bc2.y) * e01.y);
            uint32_t p2 = pack2((accC[1][nt][0] + bc2.x) * e10.x,
                                (accC[1][nt][1] + bc2.y) * e10.y);
            uint32_t p3 = pack2((accC[1][nt][2] + bc2.x) * e11.x,
                                (accC[1][nt][3] + bc2.y) * e11.y);
            uint32_t ch = (uint32_t)(n0 >> 3) + (uint32_t)nt;
            stsm4(slice + 10240u + a16(srow, ch), p0, p1, p2, p3);
        }
        pbar(pair);    // h visible to both warps

        // 5. GEMM3: o = h @ Wfc^T (reuse accC)
        #pragma unroll
        for (int mt = 0; mt < 2; mt++)
            #pragma unroll
            for (int nt = 0; nt < 8; nt++)
                accC[mt][nt][0] = accC[mt][nt][1] = accC[mt][nt][2] = accC[mt][nt][3] = 0.f;
        #pragma unroll
        for (int kt = 0; kt < 8; kt++) {
            uint32_t A0[4], A1[4];
            uint32_t ua = ((2u * kt + ksel) ^ key8) << 4;
            ldsm4(A0, hBa + ua);
            ldsm4(A1, hBa + 4096u + ua);
            #pragma unroll
            for (int p = 0; p < 4; p++) {
                uint32_t B[4];
                ldsm4(B, wf0 + (uint32_t)p * 4096u + ua);
                mma16(accC[0][2 * p],     A0, B[0], B[2]);
                mma16(accC[0][2 * p + 1], A0, B[1], B[3]);
                mma16(accC[1][2 * p],     A1, B[0], B[2]);
                mma16(accC[1][2 * p + 1], A1, B[1], B[3]);
            }
        }

        // 6. epilogue: tanh + reduce all 32 mailbox rows (in-warp: mt covers rows)
        {
            const int node = tile * 8 + pair;
            float v[16];
            #pragma unroll
            for (int nt = 0; nt < 8; nt++) {
                int c = n0 + nt * 8 + 2 * tg;
                float2 bf2 = *(float2*)(bF + c);
                v[2 * nt]     = ftanh(accC[0][nt][0] + bf2.x) + ftanh(accC[0][nt][2] + bf2.x)
                              + ftanh(accC[1][nt][0] + bf2.x) + ftanh(accC[1][nt][2] + bf2.x);
                v[2 * nt + 1] = ftanh(accC[0][nt][1] + bf2.y) + ftanh(accC[0][nt][3] + bf2.y)
                              + ftanh(accC[1][nt][1] + bf2.y) + ftanh(accC[1][nt][3] + bf2.y);
            }
            #pragma unroll
            for (int m = 4; m < 32; m <<= 1) {
                #pragma unroll
                for (int i = 0; i < 16; i++)
                    v[i] += __shfl_xor_sync(0xffffffffu, v[i], m);
            }
            if (lane < 4) {
                #pragma unroll
                for (int nt = 0; nt < 8; nt++) {
                    float2 o = {v[2 * nt], v[2 * nt + 1]};
                    *(float2*)(out + (size_t)node * 128 + n0 + nt * 8 + 2 * tg) = o;
                }
            }
        }
    }
}

extern "C" void kernel_launch(void* const* d_in, const int* in_sizes, int n_in,
                              void* d_out, int out_size)
{
    const float* src = (const float*)d_in[0];
    const float* he  = (const float*)d_in[1];
    const float* Wcf = (const float*)d_in[2];
    const float* bcf = (const float*)d_in[3];
    const float* Wdf = (const float*)d_in[4];
    const float* bdf = (const float*)d_in[5];
    const float* Wfc = (const float*)d_in[6];
    const float* bfc = (const float*)d_in[7];
    float* out = (float*)d_out;

    int ntiles = in_sizes[0] / 32768;   // 256 pairs (8 nodes) per tile

    int nsm = 148;
    cudaDeviceGetAttribute(&nsm, cudaDevAttrMultiProcessorCount, 0);
    int grid = nsm < ntiles ? nsm : ntiles;

    cudaFuncSetAttribute(dtnn_kernel, cudaFuncAttributeMaxDynamicSharedMemorySize,
                         (int)SMEM_BYTES);
    dtnn_kernel<<<grid, TPB, SMEM_BYTES>>>(src, he, Wcf, bcf, Wdf, bdf, Wfc, bfc,
                                           out, ntiles);
}

// round 11
// speedup vs baseline: 1.0609x; 1.0609x over previous
#include <cuda_runtime.h>
#include <cuda_fp16.h>
#include <cstdint>

#define TPB 512

// smem layout
#define OF_WC 0u             // 32KB fp16 Wcf (128 rows x 256B, swizzled)
#define OF_WF 32768u         // 32KB fp16 Wfc
#define OF_WD 65536u         // 8KB  fp16 Wdf (128 rows x 64B, swizzled), persistent
#define SLICE(q) (73728u + (uint32_t)(q) * 36864u)   // per-quad slice, 4 quads
//   +0     : fp16 src/h 64x128 (16KB), gate overwrites in place
//   +16384 : fp16 he 64x32 (4KB)
//   +20480 : fp32 staging, 32 rows of src (16KB), double-pumped per chunk
#define OF_BC 221184u
#define OF_BD 221696u
#define OF_BF 222208u
#define OF_MB 222720u        // 4 x 8B mbarriers
#define SMEM_BYTES 222752u

__device__ __forceinline__ void ldsm4(uint32_t r[4], uint32_t a) {
    asm volatile("ldmatrix.sync.aligned.m8n8.x4.shared.b16 {%0,%1,%2,%3}, [%4];"
                 : "=r"(r[0]), "=r"(r[1]), "=r"(r[2]), "=r"(r[3]) : "r"(a));
}

__device__ __forceinline__ void stsm4(uint32_t a, uint32_t r0, uint32_t r1,
                                      uint32_t r2, uint32_t r3) {
    asm volatile("stmatrix.sync.aligned.m8n8.x4.shared.b16 [%0], {%1,%2,%3,%4};"
                 :: "r"(a), "r"(r0), "r"(r1), "r"(r2), "r"(r3) : "memory");
}

__device__ __forceinline__ void mma16(float* c, const uint32_t* a, uint32_t b0, uint32_t b1) {
    asm volatile(
        "mma.sync.aligned.m16n8k16.row.col.f32.f16.f16.f32 "
        "{%0,%1,%2,%3}, {%4,%5,%6,%7}, {%8,%9}, {%0,%1,%2,%3};\n"
        : "+f"(c[0]), "+f"(c[1]), "+f"(c[2]), "+f"(c[3])
        : "r"(a[0]), "r"(a[1]), "r"(a[2]), "r"(a[3]), "r"(b0), "r"(b1));
}

// f16-accumulator mma (d/c are 2x half2 regs) — used for GEMM2 only (K=32)
__device__ __forceinline__ void mma16h(uint32_t* c, const uint32_t* a, uint32_t b0, uint32_t b1) {
    asm volatile(
        "mma.sync.aligned.m16n8k16.row.col.f16.f16.f16.f16 "
        "{%0,%1}, {%2,%3,%4,%5}, {%6,%7}, {%0,%1};\n"
        : "+r"(c[0]), "+r"(c[1])
        : "r"(a[0]), "r"(a[1]), "r"(a[2]), "r"(a[3]), "r"(b0), "r"(b1));
}

__device__ __forceinline__ float ftanh(float x) {
    float r;
    asm("tanh.approx.f32 %0, %1;" : "=f"(r) : "f"(x));
    return r;
}

__device__ __forceinline__ uint32_t pack2(float a, float b) {
    __half2 h = __floats2half2_rn(a, b);
    return *(uint32_t*)&h;
}
__device__ __forceinline__ float2 unp2(uint32_t u) {
    __half2 h = *(__half2*)&u;
    return __half22float2(h);
}

// quad-scoped named barrier (128 threads)
__device__ __forceinline__ void qbar(int quad) {
    asm volatile("bar.sync %0, 128;" :: "r"(quad + 1) : "memory");
}

__device__ __forceinline__ void mb_init(uint32_t mbar, uint32_t cnt) {
    asm volatile("mbarrier.init.shared.b64 [%0], %1;" :: "r"(mbar), "r"(cnt) : "memory");
}
__device__ __forceinline__ void mb_expect(uint32_t mbar, uint32_t tx) {
    asm volatile("mbarrier.arrive.expect_tx.shared.b64 _, [%0], %1;"
                 :: "r"(mbar), "r"(tx) : "memory");
}
__device__ __forceinline__ void mb_wait(uint32_t mbar, uint32_t parity) {
    asm volatile("{\n\t.reg .pred P1;\n\t"
        "W_%=:\n\t"
        "mbarrier.try_wait.parity.acquire.cta.shared::cta.b64 P1, [%0], %1, 0x989680;\n\t"
        "@P1 bra.uni D_%=;\n\t"
        "bra.uni W_%=;\n\t"
        "D_%=:\n\t}"
        :: "r"(mbar), "r"(parity) : "memory");
}
__device__ __forceinline__ void bulk_g2s(uint32_t dst, const void* src,
                                         uint32_t bytes, uint32_t mbar) {
    asm volatile("cp.async.bulk.shared::cta.global.mbarrier::complete_tx::bytes "
                 "[%0], [%1], %2, [%3];"
                 :: "r"(dst), "l"(src), "r"(bytes), "r"(mbar) : "memory");
}
#define PROXY_FENCE() asm volatile("fence.proxy.async.shared::cta;" ::: "memory")

// 256B-row swizzled addr (128 fp16 cols): ch 0..15
__device__ __forceinline__ uint32_t a16(uint32_t row, uint32_t ch) {
    return row * 256u + ((ch ^ (row & 7u)) << 4);
}
// 64B-row swizzled addr (32 fp16 cols): ch 0..3
__device__ __forceinline__ uint32_t h16(uint32_t row, uint32_t ch) {
    return row * 64u + ((ch ^ ((row >> 1) & 3u)) << 4);
}

__global__ void __launch_bounds__(TPB, 1)
dtnn_kernel(const float* __restrict__ gsrc, const float* __restrict__ ghe,
            const float* __restrict__ Wcf,  const float* __restrict__ bcf,
            const float* __restrict__ Wdf,  const float* __restrict__ bdf,
            const float* __restrict__ Wfc,  const float* __restrict__ bfc,
            float* __restrict__ out, int nchunks)
{
    extern __shared__ __align__(1024) unsigned char sm[];
    uint32_t smb;
    asm("{.reg .u64 t; cvta.to.shared.u64 t, %1; cvt.u32.u64 %0, t;}"
        : "=r"(smb) : "l"(sm));

    float* bC = (float*)(sm + OF_BC);
    float* bD = (float*)(sm + OF_BD);
    float* bF = (float*)(sm + OF_BF);

    const int tid  = threadIdx.x;
    const int lane = tid & 31;
    const int wid  = tid >> 5;
    const int tg   = lane & 3;
    const int quad = wid >> 2;            // owns a 64-row (2-node) chunk stream
    const int qtid = tid & 127;
    const int n0   = (wid & 3) * 32;      // column quarter
    const uint32_t mbar = smb + OF_MB + (uint32_t)quad * 8u;
    const int stride = gridDim.x * 4;
    const int q0 = blockIdx.x * 4 + quad; // first chunk for this quad

    // ---- mbarrier init, then prologue bulk (overlaps weight staging) ----
    if (tid < 4) {
        mb_init(smb + OF_MB + (uint32_t)tid * 8u, 1u);
        PROXY_FENCE();
    }
    __syncthreads();
    if (qtid == 0 && q0 < nchunks) {
        mb_expect(mbar, 16384u);
        bulk_g2s(smb + (SLICE(quad) - 0u) + 20480u, gsrc + (size_t)q0 * 8192,
                 16384u, mbar);
    }

    // ---- one-time weight + bias staging ----
    for (int i = tid; i < 2048; i += TPB) {
        int row = i >> 4, ch = i & 15;
        float4 u = ((const float4*)Wcf)[row * 32 + ch * 2];
        float4 v = ((const float4*)Wcf)[row * 32 + ch * 2 + 1];
        uint4 w = {pack2(u.x, u.y), pack2(u.z, u.w), pack2(v.x, v.y), pack2(v.z, v.w)};
        *(uint4*)(sm + OF_WC + a16(row, ch)) = w;
        u = ((const float4*)Wfc)[row * 32 + ch * 2];
        v = ((const float4*)Wfc)[row * 32 + ch * 2 + 1];
        uint4 w2 = {pack2(u.x, u.y), pack2(u.z, u.w), pack2(v.x, v.y), pack2(v.z, v.w)};
        *(uint4*)(sm + OF_WF + a16(row, ch)) = w2;
    }
    for (int i = tid; i < 512; i += TPB) {
        int row = i >> 2, ch = i & 3;
        float4 u = ((const float4*)Wdf)[row * 8 + ch * 2];
        float4 v = ((const float4*)Wdf)[row * 8 + ch * 2 + 1];
        uint4 w = {pack2(u.x, u.y), pack2(u.z, u.w), pack2(v.x, v.y), pack2(v.z, v.w)};
        *(uint4*)(sm + OF_WD + h16(row, ch)) = w;
    }
    if (tid < 128) { bC[tid] = bcf[tid]; bD[tid] = bdf[tid]; bF[tid] = bfc[tid]; }
    __syncthreads();

    // ---- per-lane ldmatrix constants ----
    const uint32_t mrow = (uint32_t)((lane & 7) | (((lane >> 3) & 1) << 3));
    const uint32_t ksel = (uint32_t)((lane >> 4) & 1);
    const uint32_t key8 = mrow & 7u;
    const uint32_t keyh = (mrow >> 1) & 3u;

    const uint32_t slice = smb + SLICE(quad);
    const uint32_t srcB = slice + mrow * 256u;           // +mt*4096 for rows 16mt..
    const uint32_t heB  = slice + 16384u + mrow * 64u;   // +mt*1024
    const uint32_t stg  = slice + 20480u;
    const uint32_t wc0  = smb + OF_WC + ((uint32_t)n0 + mrow) * 256u;  // +p*4096
    const uint32_t wf0  = smb + OF_WF + ((uint32_t)n0 + mrow) * 256u;
    const uint32_t wd0  = smb + OF_WD + ((uint32_t)n0 + mrow) * 64u;   // +p*1024
    const uint32_t srow = (uint32_t)(((lane >> 4) & 1) * 16 + ((lane >> 3) & 1) * 8
                                     + (lane & 7));

    uint32_t ph = 0;

    for (int c = q0; c < nchunks; c += stride) {
        // 0. half0 staged; prev chunk's GEMM3/h reads finished before overwrite
        mb_wait(mbar, ph); ph ^= 1;
        qbar(quad);

        // 1. convert half0 (rows 0-31) fp32 -> fp16 swizzled
        {
            const float4* sg = (const float4*)(sm + (stg - smb));
            #pragma unroll
            for (int it = 0; it < 4; it++) {
                int i = qtid + it * 128;           // 512 16B chunks
                int row = i >> 4, ch = i & 15;
                float4 u = sg[row * 32 + ch * 2];
                float4 v = sg[row * 32 + ch * 2 + 1];
                uint4 w = {pack2(u.x, u.y), pack2(u.z, u.w),
                           pack2(v.x, v.y), pack2(v.z, v.w)};
                *(uint4*)(sm + (slice - smb) + a16((uint32_t)row, (uint32_t)ch)) = w;
            }
        }
        qbar(quad);    // staging free

        // 2. bulk half1 (rows 32-63)
        if (qtid == 0) {
            PROXY_FENCE();
            mb_expect(mbar, 16384u);
            bulk_g2s(stg, gsrc + (size_t)c * 8192 + 4096, 16384u, mbar);
        }

        // 3. he: direct LDG fp32 -> fp16 swizzled (64 rows x 32 cols)
        {
            const float4* hp = (const float4*)(ghe + (size_t)c * 2048);
            #pragma unroll
            for (int it = 0; it < 2; it++) {
                int j = qtid + it * 128;           // 256 16B out-chunks
                int row = j >> 2, ch = j & 3;
                float4 u = hp[j * 2];
                float4 v = hp[j * 2 + 1];
                uint4 w = {pack2(u.x, u.y), pack2(u.z, u.w),
                           pack2(v.x, v.y), pack2(v.z, v.w)};
                *(uint4*)(sm + (slice - smb) + 16384u
                          + h16((uint32_t)row, (uint32_t)ch)) = w;
            }
        }

        // 4. half1 staged -> convert (rows 32-63)
        mb_wait(mbar, ph); ph ^= 1;
        {
            const float4* sg = (const float4*)(sm + (stg - smb));
            #pragma unroll
            for (int it = 0; it < 4; it++) {
                int i = qtid + it * 128;
                int row = i >> 4, ch = i & 15;
                float4 u = sg[row * 32 + ch * 2];
                float4 v = sg[row * 32 + ch * 2 + 1];
                uint4 w = {pack2(u.x, u.y), pack2(u.z, u.w),
                           pack2(v.x, v.y), pack2(v.z, v.w)};
                *(uint4*)(sm + (slice - smb) + a16((uint32_t)(row + 32), (uint32_t)ch)) = w;
            }
        }
        qbar(quad);    // src + he fully visible; staging free

        // 5. prefetch next chunk half0
        if (qtid == 0 && c + stride < nchunks) {
            PROXY_FENCE();
            mb_expect(mbar, 16384u);
            bulk_g2s(stg, gsrc + (size_t)(c + stride) * 8192, 16384u, mbar);
        }

        // 6. GEMM1: accC = src @ Wcf^T  (64x32 per warp)
        float accC[4][4][4];
        #pragma unroll
        for (int mt = 0; mt < 4; mt++)
            #pragma unroll
            for (int nt = 0; nt < 4; nt++)
                accC[mt][nt][0] = accC[mt][nt][1] = accC[mt][nt][2] = accC[mt][nt][3] = 0.f;
        #pragma unroll
        for (int kt = 0; kt < 8; kt++) {
            uint32_t ua = ((2u * kt + ksel) ^ key8) << 4;
            uint32_t B0[4], B1[4];
            ldsm4(B0, wc0 + ua);
            ldsm4(B1, wc0 + 4096u + ua);
            #pragma unroll
            for (int mt = 0; mt < 4; mt++) {
                uint32_t A[4];
                ldsm4(A, srcB + (uint32_t)mt * 4096u + ua);
                mma16(accC[mt][0], A, B0[0], B0[2]);
                mma16(accC[mt][1], A, B0[1], B0[3]);
                mma16(accC[mt][2], A, B1[0], B1[2]);
                mma16(accC[mt][3], A, B1[1], B1[3]);
            }
        }

        // 7. GEMM2 (f16 acc): accEp = he @ Wdf^T + bdf  (bias in initializer)
        uint32_t accEp[4][4][2];
        {
            uint32_t bini[4];
            #pragma unroll
            for (int nt = 0; nt < 4; nt++) {
                int cc = n0 + nt * 8 + 2 * tg;
                float2 bd2 = *(float2*)(bD + cc);
                bini[nt] = pack2(bd2.x, bd2.y);
            }
            #pragma unroll
            for (int mt = 0; mt < 4; mt++)
                #pragma unroll
                for (int nt = 0; nt < 4; nt++) {
                    accEp[mt][nt][0] = bini[nt];
                    accEp[mt][nt][1] = bini[nt];
                }
            #pragma unroll
            for (int kt = 0; kt < 2; kt++) {
                uint32_t ua = ((2u * kt + ksel) ^ keyh) << 4;
                uint32_t D0[4], D1[4];
                ldsm4(D0, wd0 + ua);
                ldsm4(D1, wd0 + 1024u + ua);
                #pragma unroll
                for (int mt = 0; mt < 4; mt++) {
                    uint32_t A[4];
                    ldsm4(A, heB + (uint32_t)mt * 1024u + ua);
                    mma16h(accEp[mt][0], A, D0[0], D0[2]);
                    mma16h(accEp[mt][1], A, D0[1], D0[3]);
                    mma16h(accEp[mt][2], A, D1[0], D1[2]);
                    mma16h(accEp[mt][3], A, D1[1], D1[3]);
                }
            }
        }
        qbar(quad);    // all warps done reading src (GEMM1) before in-place gate

        // 8. gate: h = (c + bcf) * e  written in place over src (stmatrix)
        #pragma unroll
        for (int mtp = 0; mtp < 2; mtp++) {
            #pragma unroll
            for (int nt = 0; nt < 4; nt++) {
                int cc = n0 + nt * 8 + 2 * tg;
                float2 bc2 = *(float2*)(bC + cc);
                int mA = 2 * mtp, mB = 2 * mtp + 1;
                float2 eA0 = unp2(accEp[mA][nt][0]);
                float2 eA1 = unp2(accEp[mA][nt][1]);
                float2 eB0 = unp2(accEp[mB][nt][0]);
                float2 eB1 = unp2(accEp[mB][nt][1]);
                uint32_t p0 = pack2((accC[mA][nt][0] + bc2.x) * eA0.x,
                                    (accC[mA][nt][1] + bc2.y) * eA0.y);
                uint32_t p1 = pack2((accC[mA][nt][2] + bc2.x) * eA1.x,
                                    (accC[mA][nt][3] + bc2.y) * eA1.y);
                uint32_t p2 = pack2((accC[mB][nt][0] + bc2.x) * eB0.x,
                                    (accC[mB][nt][1] + bc2.y) * eB0.y);
                uint32_t p3 = pack2((accC[mB][nt][2] + bc2.x) * eB1.x,
                                    (accC[mB][nt][3] + bc2.y) * eB1.y);
                uint32_t ch = (uint32_t)(n0 >> 3) + (uint32_t)nt;
                stsm4(slice + a16(srow + (uint32_t)mtp * 32u, ch), p0, p1, p2, p3);
            }
        }
        qbar(quad);    // h visible

        // 9. GEMM3: accO = h @ Wfc^T (reuse accC)
        #pragma unroll
        for (int mt = 0; mt < 4; mt++)
            #pragma unroll
            for (int nt = 0; nt < 4; nt++)
                accC[mt][nt][0] = accC[mt][nt][1] = accC[mt][nt][2] = accC[mt][nt][3] = 0.f;
        #pragma unroll
        for (int kt = 0; kt < 8; kt++) {
            uint32_t ua = ((2u * kt + ksel) ^ key8) << 4;
            uint32_t B0[4], B1[4];
            ldsm4(B0, wf0 + ua);
            ldsm4(B1, wf0 + 4096u + ua);
            #pragma unroll
            for (int mt = 0; mt < 4; mt++) {
                uint32_t A[4];
                ldsm4(A, srcB + (uint32_t)mt * 4096u + ua);
                mma16(accC[mt][0], A, B0[0], B0[2]);
                mma16(accC[mt][1], A, B0[1], B0[3]);
                mma16(accC[mt][2], A, B1[0], B1[2]);
                mma16(accC[mt][3], A, B1[1], B1[3]);
            }
        }

        // 10. epilogue: tanh + mailbox reduce; 2 nodes per chunk (mt pairs)
        #pragma unroll
        for (int nd = 0; nd < 2; nd++) {
            const int node = c * 2 + nd;
            const int mA = 2 * nd, mB = 2 * nd + 1;
            float v[8];
            #pragma unroll
            for (int nt = 0; nt < 4; nt++) {
                int cc = n0 + nt * 8 + 2 * tg;
                float2 bf2 = *(float2*)(bF + cc);
                v[2 * nt]     = ftanh(accC[mA][nt][0] + bf2.x) + ftanh(accC[mA][nt][2] + bf2.x)
                              + ftanh(accC[mB][nt][0] + bf2.x) + ftanh(accC[mB][nt][2] + bf2.x);
                v[2 * nt + 1] = ftanh(accC[mA][nt][1] + bf2.y) + ftanh(accC[mA][nt][3] + bf2.y)
                              + ftanh(accC[mB][nt][1] + bf2.y) + ftanh(accC[mB][nt][3] + bf2.y);
            }
            #pragma unroll
            for (int m = 4; m < 32; m <<= 1) {
                #pragma unroll
                for (int i = 0; i < 8; i++)
                    v[i] += __shfl_xor_sync(0xffffffffu, v[i], m);
            }
            if (lane < 4) {
                #pragma unroll
                for (int nt = 0; nt < 4; nt++) {
                    float2 o = {v[2 * nt], v[2 * nt + 1]};
                    *(float2*)(out + (size_t)node * 128 + n0 + nt * 8 + 2 * tg) = o;
                }
            }
        }
    }
}

extern "C" void kernel_launch(void* const* d_in, const int* in_sizes, int n_in,
                              void* d_out, int out_size)
{
    const float* src = (const float*)d_in[0];
    const float* he  = (const float*)d_in[1];
    const float* Wcf = (const float*)d_in[2];
    const float* bcf = (const float*)d_in[3];
    const float* Wdf = (const float*)d_in[4];
    const float* bdf = (const float*)d_in[5];
    const float* Wfc = (const float*)d_in[6];
    const float* bfc = (const float*)d_in[7];
    float* out = (float*)d_out;

    int nchunks = in_sizes[0] / 8192;   // 64 pairs (2 nodes) per chunk

    int nsm = 148;
    cudaDeviceGetAttribute(&nsm, cudaDevAttrMultiProcessorCount, 0);
    int grid = nsm;
    if (grid * 4 > nchunks) grid = (nchunks + 3) / 4;

    cudaFuncSetAttribute(dtnn_kernel, cudaFuncAttributeMaxDynamicSharedMemorySize,
                         (int)SMEM_BYTES);
    dtnn_kernel<<<grid, TPB, SMEM_BYTES>>>(src, he, Wcf, bcf, Wdf, bdf, Wfc, bfc,
                                           out, nchunks);
}